// round 4
// baseline (speedup 1.0000x reference)
#include <cuda_runtime.h>
#include <math.h>

#define BB 2
#define TT 2048
#define CC 1024
#define HH 16
#define DD 64
#define MROWS (BB*TT)   // 4096

// Scratch (device globals: allocation-free, graph-safe). 64 MB total.
__device__ float g_q[BB*HH*TT*DD];   // [B,H,T,D]
__device__ float g_k[BB*HH*TT*DD];
__device__ float g_v[BB*HH*TT*DD];
__device__ float g_att[BB*TT*CC];    // [B,T,H*D]

// ---------------------------------------------------------------------------
// SGEMM:  Y[m,n] = sum_k A[m,k] * W[n,k] + bias[n]
// M=4096, N=1024, K=1024. CTA tile 128x128, BK=8, 256 threads, 8x8 per thread.
// mode 0/1/2: write to g_q/g_k/g_v in [B,H,T,D] layout (A = x).
// mode 3:     A = g_att, write plain [M,N] row-major to dst_out.
// ---------------------------------------------------------------------------
__global__ __launch_bounds__(256) void gemm_kernel(
    const float* __restrict__ A_in, const float* __restrict__ W,
    const float* __restrict__ bias, float* __restrict__ dst_out, int mode)
{
    __shared__ float As[8][128];   // [k][m]
    __shared__ float Ws[8][128];   // [k][n]

    const float* __restrict__ A = (mode == 3) ? g_att : A_in;
    float* __restrict__ dst =
        (mode == 0) ? g_q : (mode == 1) ? g_k : (mode == 2) ? g_v : dst_out;

    const int tid = threadIdx.x;
    const int tx = tid & 15;          // 0..15 -> n
    const int ty = tid >> 4;          // 0..15 -> m
    const int m0 = blockIdx.y * 128;
    const int n0 = blockIdx.x * 128;

    const int lrow = tid >> 1;        // 0..127
    const int lk   = (tid & 1) * 4;   // 0 or 4

    float acc[8][8];
    #pragma unroll
    for (int i = 0; i < 8; i++)
        #pragma unroll
        for (int j = 0; j < 8; j++) acc[i][j] = 0.f;

    for (int k0 = 0; k0 < 1024; k0 += 8) {
        float4 av = *(const float4*)&A[(m0 + lrow) * 1024 + k0 + lk];
        float4 wv = *(const float4*)&W[(n0 + lrow) * 1024 + k0 + lk];
        __syncthreads();   // previous iteration's compute done reading smem
        As[lk+0][lrow] = av.x; As[lk+1][lrow] = av.y;
        As[lk+2][lrow] = av.z; As[lk+3][lrow] = av.w;
        Ws[lk+0][lrow] = wv.x; Ws[lk+1][lrow] = wv.y;
        Ws[lk+2][lrow] = wv.z; Ws[lk+3][lrow] = wv.w;
        __syncthreads();

        #pragma unroll
        for (int kk = 0; kk < 8; kk++) {
            float4 a0 = *(const float4*)&As[kk][ty*8];
            float4 a1 = *(const float4*)&As[kk][ty*8+4];
            float4 b0 = *(const float4*)&Ws[kk][tx*8];
            float4 b1 = *(const float4*)&Ws[kk][tx*8+4];
            float ar[8] = {a0.x,a0.y,a0.z,a0.w,a1.x,a1.y,a1.z,a1.w};
            float br[8] = {b0.x,b0.y,b0.z,b0.w,b1.x,b1.y,b1.z,b1.w};
            #pragma unroll
            for (int i = 0; i < 8; i++)
                #pragma unroll
                for (int j = 0; j < 8; j++)
                    acc[i][j] = fmaf(ar[i], br[j], acc[i][j]);
        }
    }

    // epilogue
    #pragma unroll
    for (int i = 0; i < 8; i++) {
        int m = m0 + ty*8 + i;
        #pragma unroll
        for (int j = 0; j < 8; j += 4) {
            int n = n0 + tx*8 + j;
            float4 bv4 = *(const float4*)&bias[n];
            float4 v;
            v.x = acc[i][j+0] + bv4.x;
            v.y = acc[i][j+1] + bv4.y;
            v.z = acc[i][j+2] + bv4.z;
            v.w = acc[i][j+3] + bv4.w;
            if (mode < 3) {
                int b = m >> 11, t = m & 2047;
                int h = n >> 6,  d = n & 63;
                *(float4*)&dst[(((b*HH + h)*TT + t)*DD) + d] = v;
            } else {
                *(float4*)&dst[m * 1024 + n] = v;
            }
        }
    }
}

// ---------------------------------------------------------------------------
// Flash attention, fp32, causal. CTA = 64 queries of one (b,h).
// 256 threads (16x16), 4x4 micro-tile of the 64x64 S tile.
// Smem: Qt[d][r], KP (Kt[d][c], reused as P[r][c]), Vs[kv][d]. 48 KB exactly.
// ---------------------------------------------------------------------------
__global__ __launch_bounds__(256) void attn_kernel()
{
    __shared__ float Qt[64][64];   // [d][qrow]
    __shared__ float KP[64][64];   // Kt[d][kvcol]  ->  P[qrow][kvcol]
    __shared__ float Vs[64][64];   // [kv][d]

    const int tid = threadIdx.x;
    const int tx = tid & 15;       // kv-col / d-col group
    const int ty = tid >> 4;       // q-row group
    const int qb = (int)gridDim.x - 1 - (int)blockIdx.x;  // heavy tiles first
    const int bh = blockIdx.y;     // b*16 + h
    const int base = bh * TT * DD;

    // Load Q tile, pre-scaled by 1/sqrt(D) = 0.125
    #pragma unroll
    for (int i = 0; i < 4; i++) {
        int l  = tid + 256*i;          // 0..1023
        int r  = l >> 4;               // 0..63
        int d0 = (l & 15) * 4;
        float4 qv = *(const float4*)&g_q[base + (qb*64 + r)*64 + d0];
        Qt[d0+0][r] = qv.x * 0.125f; Qt[d0+1][r] = qv.y * 0.125f;
        Qt[d0+2][r] = qv.z * 0.125f; Qt[d0+3][r] = qv.w * 0.125f;
    }

    float acc[4][4];
    float m_i[4], l_i[4];
    #pragma unroll
    for (int i = 0; i < 4; i++) {
        m_i[i] = -1e30f; l_i[i] = 0.f;
        #pragma unroll
        for (int j = 0; j < 4; j++) acc[i][j] = 0.f;
    }

    for (int j = 0; j <= qb; j++) {
        __syncthreads();   // previous PV done reading KP/Vs; also covers Qt fill
        #pragma unroll
        for (int i = 0; i < 4; i++) {
            int l  = tid + 256*i;
            int r  = l >> 4;
            int d0 = (l & 15) * 4;
            float4 kv = *(const float4*)&g_k[base + (j*64 + r)*64 + d0];
            KP[d0+0][r] = kv.x; KP[d0+1][r] = kv.y;
            KP[d0+2][r] = kv.z; KP[d0+3][r] = kv.w;
            float4 vv = *(const float4*)&g_v[base + (j*64 + r)*64 + d0];
            *(float4*)&Vs[r][d0] = vv;
        }
        __syncthreads();

        // S = Q K^T (scaled already)
        float s[4][4];
        #pragma unroll
        for (int i = 0; i < 4; i++)
            #pragma unroll
            for (int jj = 0; jj < 4; jj++) s[i][jj] = 0.f;

        #pragma unroll 16
        for (int d = 0; d < 64; d++) {
            float4 q4 = *(const float4*)&Qt[d][ty*4];
            float4 k4 = *(const float4*)&KP[d][tx*4];
            float qr[4] = {q4.x, q4.y, q4.z, q4.w};
            float kr[4] = {k4.x, k4.y, k4.z, k4.w};
            #pragma unroll
            for (int i = 0; i < 4; i++)
                #pragma unroll
                for (int jj = 0; jj < 4; jj++)
                    s[i][jj] = fmaf(qr[i], kr[jj], s[i][jj]);
        }

        // Causal mask (only the diagonal tile is partial)
        if (j == qb) {
            #pragma unroll
            for (int i = 0; i < 4; i++)
                #pragma unroll
                for (int jj = 0; jj < 4; jj++)
                    if (tx*4 + jj > ty*4 + i) s[i][jj] = -1e30f;
        }

        // Online softmax per row (16-lane shuffle reductions)
        #pragma unroll
        for (int i = 0; i < 4; i++) {
            float mx = fmaxf(fmaxf(s[i][0], s[i][1]), fmaxf(s[i][2], s[i][3]));
            #pragma unroll
            for (int off = 8; off >= 1; off >>= 1)
                mx = fmaxf(mx, __shfl_xor_sync(0xffffffffu, mx, off, 16));
            float mnew  = fmaxf(m_i[i], mx);
            float alpha = __expf(m_i[i] - mnew);
            float rs = 0.f;
            #pragma unroll
            for (int jj = 0; jj < 4; jj++) {
                s[i][jj] = __expf(s[i][jj] - mnew);
                rs += s[i][jj];
            }
            #pragma unroll
            for (int off = 8; off >= 1; off >>= 1)
                rs += __shfl_xor_sync(0xffffffffu, rs, off, 16);
            l_i[i] = l_i[i] * alpha + rs;
            m_i[i] = mnew;
            #pragma unroll
            for (int jj = 0; jj < 4; jj++) acc[i][jj] *= alpha;
        }

        __syncthreads();   // everyone done reading Kt from KP
        #pragma unroll
        for (int i = 0; i < 4; i++)
            *(float4*)&KP[ty*4 + i][tx*4] = make_float4(s[i][0], s[i][1], s[i][2], s[i][3]);
        __syncthreads();

        // O += P V
        #pragma unroll 8
        for (int kc = 0; kc < 64; kc++) {
            float4 v4 = *(const float4*)&Vs[kc][tx*4];
            #pragma unroll
            for (int i = 0; i < 4; i++) {
                float p = KP[ty*4 + i][kc];
                acc[i][0] = fmaf(p, v4.x, acc[i][0]);
                acc[i][1] = fmaf(p, v4.y, acc[i][1]);
                acc[i][2] = fmaf(p, v4.z, acc[i][2]);
                acc[i][3] = fmaf(p, v4.w, acc[i][3]);
            }
        }
    }

    // Epilogue: O /= l, write [B,T,H*D]
    const int b = bh >> 4, h = bh & 15;
    #pragma unroll
    for (int i = 0; i < 4; i++) {
        float inv = 1.0f / l_i[i];
        int t = qb*64 + ty*4 + i;
        float4 o = make_float4(acc[i][0]*inv, acc[i][1]*inv,
                               acc[i][2]*inv, acc[i][3]*inv);
        *(float4*)&g_att[((b*TT + t)*HH + h)*DD + tx*4] = o;
    }
}

// ---------------------------------------------------------------------------
extern "C" void kernel_launch(void* const* d_in, const int* in_sizes, int n_in,
                              void* d_out, int out_size)
{
    (void)in_sizes; (void)n_in; (void)out_size;
    const float* x  = (const float*)d_in[0];
    const float* Wq = (const float*)d_in[1];
    const float* bq = (const float*)d_in[2];
    const float* Wk = (const float*)d_in[3];
    const float* bk = (const float*)d_in[4];
    const float* Wv = (const float*)d_in[5];
    const float* bv = (const float*)d_in[6];
    const float* Wp = (const float*)d_in[7];
    const float* bp = (const float*)d_in[8];
    float* out = (float*)d_out;

    dim3 ggrid(CC/128, MROWS/128);   // (8, 32)
    gemm_kernel<<<ggrid, 256>>>(x, Wq, bq, nullptr, 0);
    gemm_kernel<<<ggrid, 256>>>(x, Wk, bk, nullptr, 1);
    gemm_kernel<<<ggrid, 256>>>(x, Wv, bv, nullptr, 2);
    attn_kernel<<<dim3(TT/64, BB*HH), 256>>>();
    gemm_kernel<<<ggrid, 256>>>(nullptr, Wp, bp, out, 3);
}

// round 5
// speedup vs baseline: 1.6116x; 1.6116x over previous
#include <cuda_runtime.h>
#include <cuda_bf16.h>
#include <math.h>
#include <stdint.h>

#define BB 2
#define TT 2048
#define CC 1024
#define HH 16
#define DD 64
#define MROWS (BB*TT)   // 4096

// ---------------- scratch (device globals; allocation-free) ----------------
__device__ float g_q[BB*HH*TT*DD];   // [B,H,T,D] fp32
__device__ float g_k[BB*HH*TT*DD];
__device__ float g_v[BB*HH*TT*DD];

__device__ __align__(256) __nv_bfloat16 g_xh[MROWS*CC];
__device__ __align__(256) __nv_bfloat16 g_xl[MROWS*CC];
__device__ __align__(256) __nv_bfloat16 g_wh[4*CC*CC];   // Wq,Wk,Wv,Wp
__device__ __align__(256) __nv_bfloat16 g_wl[4*CC*CC];
__device__ __align__(256) __nv_bfloat16 g_ath[MROWS*CC]; // attention out hi
__device__ __align__(256) __nv_bfloat16 g_atl[MROWS*CC]; // attention out lo

// ---------------------------------------------------------------------------
// fp32 -> bf16 hi/lo split.  slot 0 -> x, slot 1..4 -> W[slot-1]
// ---------------------------------------------------------------------------
__global__ void split_kernel(const float* __restrict__ src, int n, int slot)
{
    __nv_bfloat16 *hi, *lo;
    if (slot == 0) { hi = g_xh; lo = g_xl; }
    else { hi = &g_wh[(slot-1)*CC*CC]; lo = &g_wl[(slot-1)*CC*CC]; }

    int i = (blockIdx.x * blockDim.x + threadIdx.x) * 8;
    if (i >= n) return;
    float4 v0 = *(const float4*)&src[i];
    float4 v1 = *(const float4*)&src[i+4];
    float vv[8] = {v0.x,v0.y,v0.z,v0.w,v1.x,v1.y,v1.z,v1.w};
    __align__(16) __nv_bfloat16 hv[8];
    __align__(16) __nv_bfloat16 lv[8];
    #pragma unroll
    for (int k = 0; k < 8; k++) {
        hv[k] = __float2bfloat16(vv[k]);
        lv[k] = __float2bfloat16(vv[k] - __bfloat162float(hv[k]));
    }
    *(uint4*)&hi[i] = *(uint4*)hv;
    *(uint4*)&lo[i] = *(uint4*)lv;
}

// ---------------------------------------------------------------------------
// MMA helpers
// ---------------------------------------------------------------------------
__device__ __forceinline__ void mma16816(float* c, const uint32_t* a, const uint32_t* b)
{
    asm volatile(
        "mma.sync.aligned.m16n8k16.row.col.f32.bf16.bf16.f32 "
        "{%0,%1,%2,%3}, {%4,%5,%6,%7}, {%8,%9}, {%0,%1,%2,%3};\n"
        : "+f"(c[0]), "+f"(c[1]), "+f"(c[2]), "+f"(c[3])
        : "r"(a[0]), "r"(a[1]), "r"(a[2]), "r"(a[3]), "r"(b[0]), "r"(b[1]));
}
__device__ __forceinline__ void ldsm4(uint32_t* d, uint32_t addr)
{
    asm volatile("ldmatrix.sync.aligned.m8n8.x4.shared.b16 {%0,%1,%2,%3}, [%4];\n"
                 : "=r"(d[0]), "=r"(d[1]), "=r"(d[2]), "=r"(d[3]) : "r"(addr));
}
__device__ __forceinline__ void cp16(uint32_t s, const void* g)
{
    asm volatile("cp.async.cg.shared.global [%0], [%1], 16;\n" :: "r"(s), "l"(g));
}
#define CP_COMMIT() asm volatile("cp.async.commit_group;\n" ::: "memory")
#define CP_WAIT1()  asm volatile("cp.async.wait_group 1;\n" ::: "memory")
#define CP_WAIT0()  asm volatile("cp.async.wait_group 0;\n" ::: "memory")

// ---------------------------------------------------------------------------
// bf16-split GEMM:  Y[m,n] = sum_k A[m,k]*W[n,k] + bias[n]
// A = Ah+Al, W = Wh+Wl; Y = AhWh + AhWl + AlWh.
// CTA 128x128, BK=64, 256 thr (8 warps of 64x32), cp.async double buffer.
// mode 0/1/2: A = x split, write g_q/g_k/g_v fp32 [B,H,T,D].
// mode 3:     A = att split, write fp32 [M,N] to dst_out.
// Dynamic smem: 2 stages * (Ah,Al,Wh,Wl each 128x64 bf16 = 16KB) = 128KB.
// ---------------------------------------------------------------------------
__global__ __launch_bounds__(256) void gemm_bf16(
    const float* __restrict__ bias, float* __restrict__ dst_out,
    int wslot, int mode)
{
    extern __shared__ char dynsmem[];
    const uint32_t smem_u32 = (uint32_t)__cvta_generic_to_shared(dynsmem);

    const __nv_bfloat16* __restrict__ Ah = (mode == 3) ? g_ath : g_xh;
    const __nv_bfloat16* __restrict__ Al = (mode == 3) ? g_atl : g_xl;
    const __nv_bfloat16* __restrict__ Wh = &g_wh[wslot*CC*CC];
    const __nv_bfloat16* __restrict__ Wl = &g_wl[wslot*CC*CC];
    float* __restrict__ dst =
        (mode == 0) ? g_q : (mode == 1) ? g_k : (mode == 2) ? g_v : dst_out;

    const int tid  = threadIdx.x;
    const int lane = tid & 31;
    const int wid  = tid >> 5;
    const int warp_m = (wid >> 2) * 64;   // 0 or 64
    const int warp_n = (wid & 3) * 32;    // 0,32,64,96
    const int m0 = blockIdx.y * 128;
    const int n0 = blockIdx.x * 128;

    float acc[4][4][4];
    #pragma unroll
    for (int a = 0; a < 4; a++)
        #pragma unroll
        for (int b = 0; b < 4; b++)
            #pragma unroll
            for (int c = 0; c < 4; c++) acc[a][b][c] = 0.f;

    // --- async tile loader: stage in {0,1}, kt = k-tile index (k0 = kt*64) ---
    auto issue = [&](int stage, int kt) {
        const uint32_t sb = smem_u32 + stage * 65536;
        const int k0 = kt * 64;
        #pragma unroll
        for (int t = 0; t < 4; t++) {
            int id  = tid + t * 256;         // 0..1023
            int row = id >> 3;               // 0..127
            int c   = id & 7;                // 16B chunk
            uint32_t soff = row * 128 + ((c ^ (row & 7)) << 4);
            long ga = (long)(m0 + row) * 1024 + k0 + c * 8;
            long gw = (long)(n0 + row) * 1024 + k0 + c * 8;
            cp16(sb +     0 + soff, Ah + ga);
            cp16(sb + 16384 + soff, Al + ga);
            cp16(sb + 32768 + soff, Wh + gw);
            cp16(sb + 49152 + soff, Wl + gw);
        }
    };

    issue(0, 0); CP_COMMIT();

    for (int kt = 0; kt < 16; kt++) {
        if (kt < 15) { issue((kt + 1) & 1, kt + 1); CP_COMMIT(); CP_WAIT1(); }
        else         { CP_WAIT0(); }
        __syncthreads();

        const uint32_t sb = smem_u32 + (kt & 1) * 65536;
        #pragma unroll
        for (int ks = 0; ks < 4; ks++) {
            // A fragments (hi & lo), 4 m16-tiles
            uint32_t ah[4][4], al[4][4];
            #pragma unroll
            for (int mi = 0; mi < 4; mi++) {
                int m = warp_m + mi * 16 + ((lane >> 3) & 1) * 8 + (lane & 7);
                int c = ks * 2 + (lane >> 4);
                uint32_t off = m * 128 + ((c ^ (m & 7)) << 4);
                ldsm4(ah[mi], sb + off);
                ldsm4(al[mi], sb + 16384 + off);
            }
            // B fragments (hi & lo), 4 n8-tiles (two x4 loads each)
            uint32_t bh[4][2], bl[4][2];
            #pragma unroll
            for (int ni = 0; ni < 2; ni++) {
                int n = warp_n + ni * 16 + (lane >> 4) * 8 + (lane & 7);
                int c = ks * 2 + ((lane >> 3) & 1);
                uint32_t off = n * 128 + ((c ^ (n & 7)) << 4);
                uint32_t tmp[4];
                ldsm4(tmp, sb + 32768 + off);
                bh[2*ni][0] = tmp[0]; bh[2*ni][1] = tmp[1];
                bh[2*ni+1][0] = tmp[2]; bh[2*ni+1][1] = tmp[3];
                ldsm4(tmp, sb + 49152 + off);
                bl[2*ni][0] = tmp[0]; bl[2*ni][1] = tmp[1];
                bl[2*ni+1][0] = tmp[2]; bl[2*ni+1][1] = tmp[3];
            }
            // 3-term split MMA
            #pragma unroll
            for (int mi = 0; mi < 4; mi++)
                #pragma unroll
                for (int j = 0; j < 4; j++) {
                    mma16816(acc[mi][j], ah[mi], bh[j]);
                    mma16816(acc[mi][j], ah[mi], bl[j]);
                    mma16816(acc[mi][j], al[mi], bh[j]);
                }
        }
        __syncthreads();
    }

    // --- epilogue ---
    #pragma unroll
    for (int mi = 0; mi < 4; mi++) {
        int m = m0 + warp_m + mi * 16 + (lane >> 2);
        #pragma unroll
        for (int j = 0; j < 4; j++) {
            int n = n0 + warp_n + j * 8 + (lane & 3) * 2;
            float2 bv = *(const float2*)&bias[n];
            float v0 = acc[mi][j][0] + bv.x;
            float v1 = acc[mi][j][1] + bv.y;
            float v2 = acc[mi][j][2] + bv.x;   // row m+8
            float v3 = acc[mi][j][3] + bv.y;
            if (mode < 3) {
                int b = m >> 11, t = m & 2047;
                int h = n >> 6,  d = n & 63;
                *(float2*)&dst[(((b*HH + h)*TT + t)*DD) + d]     = make_float2(v0, v1);
                int t2 = (m + 8) & 2047;   // m+8 stays in same b (128-row tiles)
                *(float2*)&dst[(((b*HH + h)*TT + t2)*DD) + d]    = make_float2(v2, v3);
            } else {
                *(float2*)&dst[(long)m * 1024 + n]       = make_float2(v0, v1);
                *(float2*)&dst[(long)(m + 8) * 1024 + n] = make_float2(v2, v3);
            }
        }
    }
}

// ---------------------------------------------------------------------------
// Flash attention, fp32, causal (unchanged from R4 except epilogue emits the
// bf16 hi/lo split of the output for the tensor-core out-projection).
// ---------------------------------------------------------------------------
__global__ __launch_bounds__(256) void attn_kernel()
{
    __shared__ float Qt[64][64];   // [d][qrow]
    __shared__ float KP[64][64];   // Kt[d][kvcol] -> P[qrow][kvcol]
    __shared__ float Vs[64][64];   // [kv][d]

    const int tid = threadIdx.x;
    const int tx = tid & 15;
    const int ty = tid >> 4;
    const int qb = (int)gridDim.x - 1 - (int)blockIdx.x;  // heavy tiles first
    const int bh = blockIdx.y;
    const int base = bh * TT * DD;

    #pragma unroll
    for (int i = 0; i < 4; i++) {
        int l  = tid + 256*i;
        int r  = l >> 4;
        int d0 = (l & 15) * 4;
        float4 qv = *(const float4*)&g_q[base + (qb*64 + r)*64 + d0];
        Qt[d0+0][r] = qv.x * 0.125f; Qt[d0+1][r] = qv.y * 0.125f;
        Qt[d0+2][r] = qv.z * 0.125f; Qt[d0+3][r] = qv.w * 0.125f;
    }

    float acc[4][4];
    float m_i[4], l_i[4];
    #pragma unroll
    for (int i = 0; i < 4; i++) {
        m_i[i] = -1e30f; l_i[i] = 0.f;
        #pragma unroll
        for (int j = 0; j < 4; j++) acc[i][j] = 0.f;
    }

    for (int j = 0; j <= qb; j++) {
        __syncthreads();
        #pragma unroll
        for (int i = 0; i < 4; i++) {
            int l  = tid + 256*i;
            int r  = l >> 4;
            int d0 = (l & 15) * 4;
            float4 kv = *(const float4*)&g_k[base + (j*64 + r)*64 + d0];
            KP[d0+0][r] = kv.x; KP[d0+1][r] = kv.y;
            KP[d0+2][r] = kv.z; KP[d0+3][r] = kv.w;
            float4 vv = *(const float4*)&g_v[base + (j*64 + r)*64 + d0];
            *(float4*)&Vs[r][d0] = vv;
        }
        __syncthreads();

        float s[4][4];
        #pragma unroll
        for (int i = 0; i < 4; i++)
            #pragma unroll
            for (int jj = 0; jj < 4; jj++) s[i][jj] = 0.f;

        #pragma unroll 16
        for (int d = 0; d < 64; d++) {
            float4 q4 = *(const float4*)&Qt[d][ty*4];
            float4 k4 = *(const float4*)&KP[d][tx*4];
            float qr[4] = {q4.x, q4.y, q4.z, q4.w};
            float kr[4] = {k4.x, k4.y, k4.z, k4.w};
            #pragma unroll
            for (int i = 0; i < 4; i++)
                #pragma unroll
                for (int jj = 0; jj < 4; jj++)
                    s[i][jj] = fmaf(qr[i], kr[jj], s[i][jj]);
        }

        if (j == qb) {
            #pragma unroll
            for (int i = 0; i < 4; i++)
                #pragma unroll
                for (int jj = 0; jj < 4; jj++)
                    if (tx*4 + jj > ty*4 + i) s[i][jj] = -1e30f;
        }

        #pragma unroll
        for (int i = 0; i < 4; i++) {
            float mx = fmaxf(fmaxf(s[i][0], s[i][1]), fmaxf(s[i][2], s[i][3]));
            #pragma unroll
            for (int off = 8; off >= 1; off >>= 1)
                mx = fmaxf(mx, __shfl_xor_sync(0xffffffffu, mx, off, 16));
            float mnew  = fmaxf(m_i[i], mx);
            float alpha = __expf(m_i[i] - mnew);
            float rs = 0.f;
            #pragma unroll
            for (int jj = 0; jj < 4; jj++) {
                s[i][jj] = __expf(s[i][jj] - mnew);
                rs += s[i][jj];
            }
            #pragma unroll
            for (int off = 8; off >= 1; off >>= 1)
                rs += __shfl_xor_sync(0xffffffffu, rs, off, 16);
            l_i[i] = l_i[i] * alpha + rs;
            m_i[i] = mnew;
            #pragma unroll
            for (int jj = 0; jj < 4; jj++) acc[i][jj] *= alpha;
        }

        __syncthreads();
        #pragma unroll
        for (int i = 0; i < 4; i++)
            *(float4*)&KP[ty*4 + i][tx*4] = make_float4(s[i][0], s[i][1], s[i][2], s[i][3]);
        __syncthreads();

        #pragma unroll 8
        for (int kc = 0; kc < 64; kc++) {
            float4 v4 = *(const float4*)&Vs[kc][tx*4];
            #pragma unroll
            for (int i = 0; i < 4; i++) {
                float p = KP[ty*4 + i][kc];
                acc[i][0] = fmaf(p, v4.x, acc[i][0]);
                acc[i][1] = fmaf(p, v4.y, acc[i][1]);
                acc[i][2] = fmaf(p, v4.z, acc[i][2]);
                acc[i][3] = fmaf(p, v4.w, acc[i][3]);
            }
        }
    }

    // epilogue: O /= l, emit bf16 hi/lo at [B,T,H*D]
    const int b = bh >> 4, h = bh & 15;
    #pragma unroll
    for (int i = 0; i < 4; i++) {
        float inv = 1.0f / l_i[i];
        int t = qb*64 + ty*4 + i;
        long idx = ((long)(b*TT + t)*HH + h)*DD + tx*4;
        float o[4] = {acc[i][0]*inv, acc[i][1]*inv, acc[i][2]*inv, acc[i][3]*inv};
        __nv_bfloat16 hv[4], lv[4];
        #pragma unroll
        for (int k = 0; k < 4; k++) {
            hv[k] = __float2bfloat16(o[k]);
            lv[k] = __float2bfloat16(o[k] - __bfloat162float(hv[k]));
        }
        __nv_bfloat162 h0; h0.x = hv[0]; h0.y = hv[1];
        __nv_bfloat162 h1; h1.x = hv[2]; h1.y = hv[3];
        __nv_bfloat162 l0; l0.x = lv[0]; l0.y = lv[1];
        __nv_bfloat162 l1; l1.x = lv[2]; l1.y = lv[3];
        *(__nv_bfloat162*)&g_ath[idx]     = h0;
        *(__nv_bfloat162*)&g_ath[idx + 2] = h1;
        *(__nv_bfloat162*)&g_atl[idx]     = l0;
        *(__nv_bfloat162*)&g_atl[idx + 2] = l1;
    }
}

// ---------------------------------------------------------------------------
extern "C" void kernel_launch(void* const* d_in, const int* in_sizes, int n_in,
                              void* d_out, int out_size)
{
    (void)in_sizes; (void)n_in; (void)out_size;
    const float* x  = (const float*)d_in[0];
    const float* Wq = (const float*)d_in[1];
    const float* bq = (const float*)d_in[2];
    const float* Wk = (const float*)d_in[3];
    const float* bk = (const float*)d_in[4];
    const float* Wv = (const float*)d_in[5];
    const float* bv = (const float*)d_in[6];
    const float* Wp = (const float*)d_in[7];
    const float* bp = (const float*)d_in[8];
    float* out = (float*)d_out;

    static bool attr_done = false;
    if (!attr_done) {
        cudaFuncSetAttribute(gemm_bf16,
            cudaFuncAttributeMaxDynamicSharedMemorySize, 131072);
        attr_done = true;
    }

    // hi/lo splits
    split_kernel<<<(MROWS*CC)/8/256, 256>>>(x,  MROWS*CC, 0);
    split_kernel<<<(CC*CC)/8/256,    256>>>(Wq, CC*CC, 1);
    split_kernel<<<(CC*CC)/8/256,    256>>>(Wk, CC*CC, 2);
    split_kernel<<<(CC*CC)/8/256,    256>>>(Wv, CC*CC, 3);
    split_kernel<<<(CC*CC)/8/256,    256>>>(Wp, CC*CC, 4);

    dim3 ggrid(CC/128, MROWS/128);   // (8, 32)
    gemm_bf16<<<ggrid, 256, 131072>>>(bq, nullptr, 0, 0);
    gemm_bf16<<<ggrid, 256, 131072>>>(bk, nullptr, 1, 1);
    gemm_bf16<<<ggrid, 256, 131072>>>(bv, nullptr, 2, 2);
    attn_kernel<<<dim3(TT/64, BB*HH), 256>>>();
    gemm_bf16<<<ggrid, 256, 131072>>>(bp, out, 3, 3);
}

// round 6
// speedup vs baseline: 2.1592x; 1.3398x over previous
#include <cuda_runtime.h>
#include <cuda_bf16.h>
#include <math.h>
#include <stdint.h>

#define BB 2
#define TT 2048
#define CC 1024
#define HH 16
#define DD 64
#define MROWS (BB*TT)   // 4096

// ---------------- scratch (device globals; allocation-free) ----------------
__device__ __align__(256) __nv_bfloat16 g_xh[MROWS*CC];
__device__ __align__(256) __nv_bfloat16 g_xl[MROWS*CC];
__device__ __align__(256) __nv_bfloat16 g_wh[4*CC*CC];   // Wq,Wk,Wv,Wp
__device__ __align__(256) __nv_bfloat16 g_wl[4*CC*CC];
__device__ __align__(256) __nv_bfloat16 g_qh[BB*HH*TT*DD]; // [B,H,T,D] scaled
__device__ __align__(256) __nv_bfloat16 g_ql[BB*HH*TT*DD];
__device__ __align__(256) __nv_bfloat16 g_kh[BB*HH*TT*DD]; // [B,H,T,D]
__device__ __align__(256) __nv_bfloat16 g_kl[BB*HH*TT*DD];
__device__ __align__(256) __nv_bfloat16 g_vth[BB*HH*DD*TT]; // [B,H,D,T]
__device__ __align__(256) __nv_bfloat16 g_vtl[BB*HH*DD*TT];
__device__ __align__(256) __nv_bfloat16 g_ath[MROWS*CC];   // attn out hi [B,T,C]
__device__ __align__(256) __nv_bfloat16 g_atl[MROWS*CC];   // attn out lo

// ---------------------------------------------------------------------------
__global__ void split_kernel(const float* __restrict__ src, int n, int slot)
{
    __nv_bfloat16 *hi, *lo;
    if (slot == 0) { hi = g_xh; lo = g_xl; }
    else { hi = &g_wh[(slot-1)*CC*CC]; lo = &g_wl[(slot-1)*CC*CC]; }

    int i = (blockIdx.x * blockDim.x + threadIdx.x) * 8;
    if (i >= n) return;
    float4 v0 = *(const float4*)&src[i];
    float4 v1 = *(const float4*)&src[i+4];
    float vv[8] = {v0.x,v0.y,v0.z,v0.w,v1.x,v1.y,v1.z,v1.w};
    __align__(16) __nv_bfloat16 hv[8];
    __align__(16) __nv_bfloat16 lv[8];
    #pragma unroll
    for (int k = 0; k < 8; k++) {
        hv[k] = __float2bfloat16(vv[k]);
        lv[k] = __float2bfloat16(vv[k] - __bfloat162float(hv[k]));
    }
    *(uint4*)&hi[i] = *(uint4*)hv;
    *(uint4*)&lo[i] = *(uint4*)lv;
}

// ---------------------------------------------------------------------------
// MMA helpers
// ---------------------------------------------------------------------------
__device__ __forceinline__ void mma16816(float* c, const uint32_t* a, const uint32_t* b)
{
    asm volatile(
        "mma.sync.aligned.m16n8k16.row.col.f32.bf16.bf16.f32 "
        "{%0,%1,%2,%3}, {%4,%5,%6,%7}, {%8,%9}, {%0,%1,%2,%3};\n"
        : "+f"(c[0]), "+f"(c[1]), "+f"(c[2]), "+f"(c[3])
        : "r"(a[0]), "r"(a[1]), "r"(a[2]), "r"(a[3]), "r"(b[0]), "r"(b[1]));
}
__device__ __forceinline__ void ldsm4(uint32_t* d, uint32_t addr)
{
    asm volatile("ldmatrix.sync.aligned.m8n8.x4.shared.b16 {%0,%1,%2,%3}, [%4];\n"
                 : "=r"(d[0]), "=r"(d[1]), "=r"(d[2]), "=r"(d[3]) : "r"(addr));
}
__device__ __forceinline__ void cp16(uint32_t s, const void* g)
{
    asm volatile("cp.async.cg.shared.global [%0], [%1], 16;\n" :: "r"(s), "l"(g));
}
#define CP_COMMIT() asm volatile("cp.async.commit_group;\n" ::: "memory")
#define CP_WAIT1()  asm volatile("cp.async.wait_group 1;\n" ::: "memory")
#define CP_WAIT0()  asm volatile("cp.async.wait_group 0;\n" ::: "memory")

__device__ __forceinline__ uint32_t pack2(float e0, float e1)
{
    __nv_bfloat162 t;
    t.x = __float2bfloat16(e0);
    t.y = __float2bfloat16(e1);
    return *(uint32_t*)&t;
}
__device__ __forceinline__ void split2(float v0, float v1,
                                       __nv_bfloat16* hi, __nv_bfloat16* lo, size_t idx)
{
    __nv_bfloat162 h, l;
    h.x = __float2bfloat16(v0);
    h.y = __float2bfloat16(v1);
    l.x = __float2bfloat16(v0 - __bfloat162float(h.x));
    l.y = __float2bfloat16(v1 - __bfloat162float(h.y));
    *(__nv_bfloat162*)&hi[idx] = h;
    *(__nv_bfloat162*)&lo[idx] = l;
}

// ---------------------------------------------------------------------------
// Generic bf16-split GEMM: Y[m,n] = sum_k A[m,k]*W[n,k] (+bias)
// CTA 128x128, BK=64, 256 thr, cp.async double buffer (128KB dyn smem).
// mode 0: Y = x Wq^T + bq, scale 0.125, split -> g_qh/g_ql [B,H,T,D]
// mode 1: same -> g_kh/g_kl
// mode 2: A=Wv, W=x_b  (Y[o][t] = V^T), bias by m, split -> g_vth/g_vtl [B,H,D,T]
// mode 3: A=att split, W=Wp, fp32 out [M,1024]
// ---------------------------------------------------------------------------
__global__ __launch_bounds__(256) void gemm_bf16(
    const __nv_bfloat16* __restrict__ Ah, const __nv_bfloat16* __restrict__ Al,
    const __nv_bfloat16* __restrict__ Wh, const __nv_bfloat16* __restrict__ Wl,
    const float* __restrict__ bias, float* __restrict__ out32,
    int mode, int bpar)
{
    extern __shared__ char dynsmem[];
    const uint32_t smem_u32 = (uint32_t)__cvta_generic_to_shared(dynsmem);

    const int tid  = threadIdx.x;
    const int lane = tid & 31;
    const int wid  = tid >> 5;
    const int warp_m = (wid >> 2) * 64;
    const int warp_n = (wid & 3) * 32;
    const int m0 = blockIdx.y * 128;
    const int n0 = blockIdx.x * 128;

    float acc[4][4][4];
    #pragma unroll
    for (int a = 0; a < 4; a++)
        #pragma unroll
        for (int b = 0; b < 4; b++)
            #pragma unroll
            for (int c = 0; c < 4; c++) acc[a][b][c] = 0.f;

    auto issue = [&](int stage, int kt) {
        const uint32_t sb = smem_u32 + stage * 65536;
        const int k0 = kt * 64;
        #pragma unroll
        for (int t = 0; t < 4; t++) {
            int id  = tid + t * 256;
            int row = id >> 3;
            int c   = id & 7;
            uint32_t soff = row * 128 + ((c ^ (row & 7)) << 4);
            long ga = (long)(m0 + row) * 1024 + k0 + c * 8;
            long gw = (long)(n0 + row) * 1024 + k0 + c * 8;
            cp16(sb +     0 + soff, Ah + ga);
            cp16(sb + 16384 + soff, Al + ga);
            cp16(sb + 32768 + soff, Wh + gw);
            cp16(sb + 49152 + soff, Wl + gw);
        }
    };

    issue(0, 0); CP_COMMIT();

    for (int kt = 0; kt < 16; kt++) {
        if (kt < 15) { issue((kt + 1) & 1, kt + 1); CP_COMMIT(); CP_WAIT1(); }
        else         { CP_WAIT0(); }
        __syncthreads();

        const uint32_t sb = smem_u32 + (kt & 1) * 65536;
        #pragma unroll
        for (int ks = 0; ks < 4; ks++) {
            uint32_t ah[4][4], al[4][4];
            #pragma unroll
            for (int mi = 0; mi < 4; mi++) {
                int m = warp_m + mi * 16 + ((lane >> 3) & 1) * 8 + (lane & 7);
                int c = ks * 2 + (lane >> 4);
                uint32_t off = m * 128 + ((c ^ (m & 7)) << 4);
                ldsm4(ah[mi], sb + off);
                ldsm4(al[mi], sb + 16384 + off);
            }
            uint32_t bh[4][2], bl[4][2];
            #pragma unroll
            for (int ni = 0; ni < 2; ni++) {
                int n = warp_n + ni * 16 + (lane >> 4) * 8 + (lane & 7);
                int c = ks * 2 + ((lane >> 3) & 1);
                uint32_t off = n * 128 + ((c ^ (n & 7)) << 4);
                uint32_t tmp[4];
                ldsm4(tmp, sb + 32768 + off);
                bh[2*ni][0] = tmp[0]; bh[2*ni][1] = tmp[1];
                bh[2*ni+1][0] = tmp[2]; bh[2*ni+1][1] = tmp[3];
                ldsm4(tmp, sb + 49152 + off);
                bl[2*ni][0] = tmp[0]; bl[2*ni][1] = tmp[1];
                bl[2*ni+1][0] = tmp[2]; bl[2*ni+1][1] = tmp[3];
            }
            #pragma unroll
            for (int mi = 0; mi < 4; mi++)
                #pragma unroll
                for (int j = 0; j < 4; j++) {
                    mma16816(acc[mi][j], ah[mi], bh[j]);
                    mma16816(acc[mi][j], ah[mi], bl[j]);
                    mma16816(acc[mi][j], al[mi], bh[j]);
                }
        }
        __syncthreads();
    }

    // --- epilogue ---
    #pragma unroll
    for (int mi = 0; mi < 4; mi++) {
        int m = m0 + warp_m + mi * 16 + (lane >> 2);
        #pragma unroll
        for (int j = 0; j < 4; j++) {
            int n = n0 + warp_n + j * 8 + (lane & 3) * 2;
            float v0, v1, v2, v3;
            if (mode == 2) {
                float bm0 = bias[m], bm1 = bias[m + 8];
                v0 = acc[mi][j][0] + bm0; v1 = acc[mi][j][1] + bm0;
                v2 = acc[mi][j][2] + bm1; v3 = acc[mi][j][3] + bm1;
            } else {
                float2 bv = *(const float2*)&bias[n];
                v0 = acc[mi][j][0] + bv.x; v1 = acc[mi][j][1] + bv.y;
                v2 = acc[mi][j][2] + bv.x; v3 = acc[mi][j][3] + bv.y;
            }
            if (mode == 0 || mode == 1) {
                if (mode == 0) { v0 *= 0.125f; v1 *= 0.125f; v2 *= 0.125f; v3 *= 0.125f; }
                __nv_bfloat16 *hi = (mode == 0) ? g_qh : g_kh;
                __nv_bfloat16 *lo = (mode == 0) ? g_ql : g_kl;
                int b = m >> 11, t = m & 2047;
                int h = n >> 6,  d = n & 63;
                size_t i0 = ((size_t)((b*HH + h)*TT + t))*DD + d;
                split2(v0, v1, hi, lo, i0);
                int t2 = (m + 8) & 2047;
                size_t i1 = ((size_t)((b*HH + h)*TT + t2))*DD + d;
                split2(v2, v3, hi, lo, i1);
            } else if (mode == 2) {
                // m = o (h*64+d), n = t, batch bpar
                int h = m >> 6, d = m & 63;
                size_t i0 = ((size_t)((bpar*HH + h)*DD + d))*TT + n;
                split2(v0, v1, g_vth, g_vtl, i0);
                int h2 = (m + 8) >> 6, d2 = (m + 8) & 63;
                size_t i1 = ((size_t)((bpar*HH + h2)*DD + d2))*TT + n;
                split2(v2, v3, g_vth, g_vtl, i1);
            } else {
                *(float2*)&out32[(long)m * 1024 + n]       = make_float2(v0, v1);
                *(float2*)&out32[(long)(m + 8) * 1024 + n] = make_float2(v2, v3);
            }
        }
    }
}

// ---------------------------------------------------------------------------
// Tensor-core flash attention (bf16 split, fp32 softmax/accum), causal.
// CTA: 128 q-rows x one (b,h). 8 warps, each 16 rows. KV tile 64, dbl-buffered.
// Dyn smem 96KB: Qh[0,16K) Ql[16K,32K) stages at 32K: {Kh,Kl,Vh,Vl} x2.
// ---------------------------------------------------------------------------
__global__ __launch_bounds__(256, 2) void attn_mma()
{
    extern __shared__ char dynsmem[];
    const uint32_t sb = (uint32_t)__cvta_generic_to_shared(dynsmem);
    const uint32_t QH = 0, QL = 16384, ST = 32768, STSZ = 32768;

    const int tid  = threadIdx.x;
    const int lane = tid & 31;
    const int wid  = tid >> 5;
    const int qi = (int)gridDim.x - 1 - (int)blockIdx.x;
    const int bh = blockIdx.y;
    const int ntiles = 2*qi + 2;
    const int wrow = wid * 16;

    const size_t qkbase = (size_t)bh * TT * DD;   // [B,H,T,D]
    const size_t vbase  = (size_t)bh * DD * TT;   // [B,H,D,T]

    // Q load (once)
    {
        int row = (tid >> 3);
        int c   = tid & 7;
        #pragma unroll
        for (int t = 0; t < 4; t++) {
            int r = row + t * 32;
            uint32_t soff = r * 128 + ((c ^ (r & 7)) << 4);
            size_t g = (qkbase + (size_t)(qi*128 + r)*DD) + c*8;
            cp16(sb + QH + soff, g_qh + g);
            cp16(sb + QL + soff, g_ql + g);
        }
    }

    auto issue_tile = [&](int j) {
        const uint32_t base = sb + ST + (j & 1) * STSZ;
        const int kv0 = j * 64;
        int row = (tid >> 3);
        int c   = tid & 7;
        #pragma unroll
        for (int half = 0; half < 2; half++) {
            int r = row + half * 32;
            uint32_t soff = r * 128 + ((c ^ (r & 7)) << 4);
            size_t gk = (qkbase + (size_t)(kv0 + r)*DD) + c*8;
            size_t gv = (vbase  + (size_t)r*TT) + kv0 + c*8;
            cp16(base +     0 + soff, g_kh  + gk);
            cp16(base +  8192 + soff, g_kl  + gk);
            cp16(base + 16384 + soff, g_vth + gv);
            cp16(base + 24576 + soff, g_vtl + gv);
        }
    };

    issue_tile(0); CP_COMMIT();

    float o[8][4];
    #pragma unroll
    for (int j = 0; j < 8; j++)
        #pragma unroll
        for (int e = 0; e < 4; e++) o[j][e] = 0.f;
    float m0 = -1e30f, m1 = -1e30f, l0 = 0.f, l1 = 0.f;

    const int r0g = qi*128 + wrow + (lane >> 2);
    const int r1g = r0g + 8;

    for (int j = 0; j < ntiles; j++) {
        if (j + 1 < ntiles) { issue_tile(j + 1); CP_COMMIT(); CP_WAIT1(); }
        else                { CP_WAIT0(); }
        __syncthreads();

        const uint32_t base = sb + ST + (j & 1) * STSZ;

        // ---- S = Q K^T ----
        float s[8][4];
        #pragma unroll
        for (int t = 0; t < 8; t++)
            #pragma unroll
            for (int e = 0; e < 4; e++) s[t][e] = 0.f;

        const int nk = (lane >> 4) * 8 + (lane & 7);
        #pragma unroll
        for (int ks = 0; ks < 4; ks++) {
            uint32_t qh[4], ql[4];
            int mq = wrow + ((lane >> 3) & 1) * 8 + (lane & 7);
            int cq = ks * 2 + (lane >> 4);
            uint32_t qoff = mq * 128 + ((cq ^ (mq & 7)) << 4);
            ldsm4(qh, sb + QH + qoff);
            ldsm4(ql, sb + QL + qoff);
            int ck = ks * 2 + ((lane >> 3) & 1);
            #pragma unroll
            for (int np = 0; np < 4; np++) {
                int n = np * 16 + nk;
                uint32_t koff = n * 128 + ((ck ^ (n & 7)) << 4);
                uint32_t kh4[4], kl4[4];
                ldsm4(kh4, base + koff);
                ldsm4(kl4, base + 8192 + koff);
                mma16816(s[2*np],   qh, kh4);     mma16816(s[2*np],   qh, kl4);
                mma16816(s[2*np],   ql, kh4);
                mma16816(s[2*np+1], qh, kh4+2);   mma16816(s[2*np+1], qh, kl4+2);
                mma16816(s[2*np+1], ql, kh4+2);
            }
        }

        // ---- causal mask ----
        const int kv0 = j * 64;
        if (kv0 + 63 > r0g) {
            #pragma unroll
            for (int t = 0; t < 8; t++) {
                int colb = kv0 + t*8 + (lane & 3)*2;
                #pragma unroll
                for (int e = 0; e < 2; e++) {
                    if (colb + e > r0g) s[t][e]   = -1e30f;
                    if (colb + e > r1g) s[t][2+e] = -1e30f;
                }
            }
        }

        // ---- online softmax ----
        float mx0 = -1e30f, mx1 = -1e30f;
        #pragma unroll
        for (int t = 0; t < 8; t++) {
            mx0 = fmaxf(mx0, fmaxf(s[t][0], s[t][1]));
            mx1 = fmaxf(mx1, fmaxf(s[t][2], s[t][3]));
        }
        mx0 = fmaxf(mx0, __shfl_xor_sync(0xffffffffu, mx0, 1));
        mx0 = fmaxf(mx0, __shfl_xor_sync(0xffffffffu, mx0, 2));
        mx1 = fmaxf(mx1, __shfl_xor_sync(0xffffffffu, mx1, 1));
        mx1 = fmaxf(mx1, __shfl_xor_sync(0xffffffffu, mx1, 2));
        float mn0 = fmaxf(m0, mx0), mn1 = fmaxf(m1, mx1);
        float a0 = __expf(m0 - mn0), a1 = __expf(m1 - mn1);
        float rs0 = 0.f, rs1 = 0.f;
        #pragma unroll
        for (int t = 0; t < 8; t++) {
            s[t][0] = __expf(s[t][0] - mn0); rs0 += s[t][0];
            s[t][1] = __expf(s[t][1] - mn0); rs0 += s[t][1];
            s[t][2] = __expf(s[t][2] - mn1); rs1 += s[t][2];
            s[t][3] = __expf(s[t][3] - mn1); rs1 += s[t][3];
        }
        rs0 += __shfl_xor_sync(0xffffffffu, rs0, 1);
        rs0 += __shfl_xor_sync(0xffffffffu, rs0, 2);
        rs1 += __shfl_xor_sync(0xffffffffu, rs1, 1);
        rs1 += __shfl_xor_sync(0xffffffffu, rs1, 2);
        l0 = l0 * a0 + rs0; l1 = l1 * a1 + rs1;
        m0 = mn0; m1 = mn1;
        #pragma unroll
        for (int t = 0; t < 8; t++) {
            o[t][0] *= a0; o[t][1] *= a0;
            o[t][2] *= a1; o[t][3] *= a1;
        }

        // ---- O += P V ----
        #pragma unroll
        for (int ks = 0; ks < 4; ks++) {
            uint32_t ph[4], pl[4];
            #pragma unroll
            for (int h2 = 0; h2 < 2; h2++) {
                int t = 2*ks + h2;
                float v0 = s[t][0], v1 = s[t][1], v2 = s[t][2], v3 = s[t][3];
                uint32_t p01 = pack2(v0, v1);
                uint32_t p23 = pack2(v2, v3);
                ph[2*h2]   = p01;
                ph[2*h2+1] = p23;
                __nv_bfloat162 b01 = *(__nv_bfloat162*)&p01;
                __nv_bfloat162 b23 = *(__nv_bfloat162*)&p23;
                pl[2*h2]   = pack2(v0 - __bfloat162float(b01.x), v1 - __bfloat162float(b01.y));
                pl[2*h2+1] = pack2(v2 - __bfloat162float(b23.x), v3 - __bfloat162float(b23.y));
            }
            int ck = ks * 2 + ((lane >> 3) & 1);
            #pragma unroll
            for (int np = 0; np < 4; np++) {
                int n = np * 16 + nk;
                uint32_t voff = n * 128 + ((ck ^ (n & 7)) << 4);
                uint32_t vh4[4], vl4[4];
                ldsm4(vh4, base + 16384 + voff);
                ldsm4(vl4, base + 24576 + voff);
                mma16816(o[2*np],   ph, vh4);     mma16816(o[2*np],   ph, vl4);
                mma16816(o[2*np],   pl, vh4);
                mma16816(o[2*np+1], ph, vh4+2);   mma16816(o[2*np+1], ph, vl4+2);
                mma16816(o[2*np+1], pl, vh4+2);
            }
        }
        __syncthreads();
    }

    // ---- epilogue: O /= l, bf16 split to [B,T,H*D] ----
    float inv0 = 1.0f / l0, inv1 = 1.0f / l1;
    const int b = bh >> 4, h = bh & 15;
    #pragma unroll
    for (int t = 0; t < 8; t++) {
        int d = t*8 + (lane & 3)*2;
        size_t i0 = ((size_t)(b*TT + r0g)*HH + h)*DD + d;
        size_t i1 = ((size_t)(b*TT + r1g)*HH + h)*DD + d;
        split2(o[t][0]*inv0, o[t][1]*inv0, g_ath, g_atl, i0);
        split2(o[t][2]*inv1, o[t][3]*inv1, g_ath, g_atl, i1);
    }
}

// ---------------------------------------------------------------------------
extern "C" void kernel_launch(void* const* d_in, const int* in_sizes, int n_in,
                              void* d_out, int out_size)
{
    (void)in_sizes; (void)n_in; (void)out_size;
    const float* x  = (const float*)d_in[0];
    const float* Wq = (const float*)d_in[1];
    const float* bq = (const float*)d_in[2];
    const float* Wk = (const float*)d_in[3];
    const float* bk = (const float*)d_in[4];
    const float* Wv = (const float*)d_in[5];
    const float* bv = (const float*)d_in[6];
    const float* Wp = (const float*)d_in[7];
    const float* bp = (const float*)d_in[8];
    float* out = (float*)d_out;

    static bool attr_done = false;
    if (!attr_done) {
        cudaFuncSetAttribute(gemm_bf16,
            cudaFuncAttributeMaxDynamicSharedMemorySize, 131072);
        cudaFuncSetAttribute(attn_mma,
            cudaFuncAttributeMaxDynamicSharedMemorySize, 98304);
        attr_done = true;
    }

    // device-symbol addresses are host-invalid; use the device pointers via
    // kernels only. For kernel args we need raw pointers: obtain via
    // cudaGetSymbolAddress once (host API, not captured as stream work).
    static __nv_bfloat16 *xh=nullptr,*xl=nullptr,*wh=nullptr,*wl=nullptr,*ath=nullptr,*atl=nullptr;
    if (!xh) {
        cudaGetSymbolAddress((void**)&xh,  g_xh);
        cudaGetSymbolAddress((void**)&xl,  g_xl);
        cudaGetSymbolAddress((void**)&wh,  g_wh);
        cudaGetSymbolAddress((void**)&wl,  g_wl);
        cudaGetSymbolAddress((void**)&ath, g_ath);
        cudaGetSymbolAddress((void**)&atl, g_atl);
    }

    // hi/lo splits
    split_kernel<<<(MROWS*CC)/8/256, 256>>>(x,  MROWS*CC, 0);
    split_kernel<<<(CC*CC)/8/256,    256>>>(Wq, CC*CC, 1);
    split_kernel<<<(CC*CC)/8/256,    256>>>(Wk, CC*CC, 2);
    split_kernel<<<(CC*CC)/8/256,    256>>>(Wv, CC*CC, 3);
    split_kernel<<<(CC*CC)/8/256,    256>>>(Wp, CC*CC, 4);

    dim3 pgrid(CC/128, MROWS/128);   // (8, 32)
    gemm_bf16<<<pgrid, 256, 131072>>>(xh, xl, wh + 0*CC*CC, wl + 0*CC*CC, bq, nullptr, 0, 0);
    gemm_bf16<<<pgrid, 256, 131072>>>(xh, xl, wh + 1*CC*CC, wl + 1*CC*CC, bk, nullptr, 1, 0);
    // V^T = Wv x_b^T : A = Wv-split, W = x_b-split, grid (T/128, 1024/128)
    dim3 vgrid(TT/128, CC/128);      // (16, 8)
    gemm_bf16<<<vgrid, 256, 131072>>>(wh + 2*CC*CC, wl + 2*CC*CC, xh,              xl,              bv, nullptr, 2, 0);
    gemm_bf16<<<vgrid, 256, 131072>>>(wh + 2*CC*CC, wl + 2*CC*CC, xh + TT*CC,      xl + TT*CC,      bv, nullptr, 2, 1);

    attn_mma<<<dim3(TT/128, BB*HH), 256, 98304>>>();

    gemm_bf16<<<pgrid, 256, 131072>>>(ath, atl, wh + 3*CC*CC, wl + 3*CC*CC, bp, out, 3, 0);
}

// round 9
// speedup vs baseline: 3.3907x; 1.5703x over previous
#include <cuda_runtime.h>
#include <cuda_bf16.h>
#include <math.h>
#include <stdint.h>

#define BB 2
#define TT 2048
#define CC 1024
#define HH 16
#define DD 64
#define MROWS (BB*TT)   // 4096

// ---------------- scratch (device globals; allocation-free) ----------------
__device__ __align__(256) __nv_bfloat16 g_xh[MROWS*CC];
__device__ __align__(256) __nv_bfloat16 g_xl[MROWS*CC];
__device__ __align__(256) __nv_bfloat16 g_wh[4*CC*CC];   // Wq,Wk,Wv,Wp
__device__ __align__(256) __nv_bfloat16 g_wl[4*CC*CC];
__device__ __align__(256) __nv_bfloat16 g_qh[BB*HH*TT*DD]; // [B,H,T,D] scaled
__device__ __align__(256) __nv_bfloat16 g_ql[BB*HH*TT*DD];
__device__ __align__(256) __nv_bfloat16 g_kh[BB*HH*TT*DD]; // [B,H,T,D]
__device__ __align__(256) __nv_bfloat16 g_kl[BB*HH*TT*DD];
__device__ __align__(256) __nv_bfloat16 g_vth[BB*HH*DD*TT]; // [B,H,D,T]
__device__ __align__(256) __nv_bfloat16 g_vtl[BB*HH*DD*TT];
__device__ __align__(256) __nv_bfloat16 g_ath[MROWS*CC];   // attn out hi [B,T,C]
__device__ __align__(256) __nv_bfloat16 g_atl[MROWS*CC];   // attn out lo

// 0.125 * log2(e): QK^T scores produced directly in log2 domain -> exp2f softmax
#define QSCALE 0.18033688f

// ---------------------------------------------------------------------------
// helpers
// ---------------------------------------------------------------------------
__device__ __forceinline__ void cp16(uint32_t s, const void* g)
{
    asm volatile("cp.async.cg.shared.global [%0], [%1], 16;\n" :: "r"(s), "l"(g));
}
#define CP_COMMIT() asm volatile("cp.async.commit_group;\n" ::: "memory")
#define CP_WAIT1()  asm volatile("cp.async.wait_group 1;\n" ::: "memory")
#define CP_WAIT0()  asm volatile("cp.async.wait_group 0;\n" ::: "memory")

// NOTE: not volatile — results/deps are fully register-carried; lets ptxas
// schedule HMMA against surrounding ALU and break same-acc issue chains.
__device__ __forceinline__ void mma16816(float* c, const uint32_t* a, const uint32_t* b)
{
    asm("mma.sync.aligned.m16n8k16.row.col.f32.bf16.bf16.f32 "
        "{%0,%1,%2,%3}, {%4,%5,%6,%7}, {%8,%9}, {%0,%1,%2,%3};\n"
        : "+f"(c[0]), "+f"(c[1]), "+f"(c[2]), "+f"(c[3])
        : "r"(a[0]), "r"(a[1]), "r"(a[2]), "r"(a[3]), "r"(b[0]), "r"(b[1]));
}
__device__ __forceinline__ void ldsm4(uint32_t* d, uint32_t addr)
{
    asm volatile("ldmatrix.sync.aligned.m8n8.x4.shared.b16 {%0,%1,%2,%3}, [%4];\n"
                 : "=r"(d[0]), "=r"(d[1]), "=r"(d[2]), "=r"(d[3]) : "r"(addr));
}
__device__ __forceinline__ uint32_t pack2(float e0, float e1)
{
    __nv_bfloat162 t;
    t.x = __float2bfloat16(e0);
    t.y = __float2bfloat16(e1);
    return *(uint32_t*)&t;
}
__device__ __forceinline__ void split2(float v0, float v1,
                                       __nv_bfloat16* hi, __nv_bfloat16* lo, size_t idx)
{
    __nv_bfloat162 h, l;
    h.x = __float2bfloat16(v0);
    h.y = __float2bfloat16(v1);
    l.x = __float2bfloat16(v0 - __bfloat162float(h.x));
    l.y = __float2bfloat16(v1 - __bfloat162float(h.y));
    *(__nv_bfloat162*)&hi[idx] = h;
    *(__nv_bfloat162*)&lo[idx] = l;
}

// ---------------------------------------------------------------------------
// splits
// ---------------------------------------------------------------------------
__global__ void split_x(const float* __restrict__ src)
{
    int i = (blockIdx.x * blockDim.x + threadIdx.x) * 8;
    float4 v0 = *(const float4*)&src[i];
    float4 v1 = *(const float4*)&src[i+4];
    float vv[8] = {v0.x,v0.y,v0.z,v0.w,v1.x,v1.y,v1.z,v1.w};
    __align__(16) __nv_bfloat16 hv[8];
    __align__(16) __nv_bfloat16 lv[8];
    #pragma unroll
    for (int k = 0; k < 8; k++) {
        hv[k] = __float2bfloat16(vv[k]);
        lv[k] = __float2bfloat16(vv[k] - __bfloat162float(hv[k]));
    }
    *(uint4*)&g_xh[i] = *(uint4*)hv;
    *(uint4*)&g_xl[i] = *(uint4*)lv;
}
__global__ void split_w4(const float* __restrict__ w0, const float* __restrict__ w1,
                         const float* __restrict__ w2, const float* __restrict__ w3)
{
    int i = (blockIdx.x * blockDim.x + threadIdx.x) * 8;   // over 4*CC*CC
    int w = i >> 20;
    const float* src = (w == 0) ? w0 : (w == 1) ? w1 : (w == 2) ? w2 : w3;
    int off = i & (CC*CC - 1);
    float4 v0 = *(const float4*)&src[off];
    float4 v1 = *(const float4*)&src[off+4];
    float vv[8] = {v0.x,v0.y,v0.z,v0.w,v1.x,v1.y,v1.z,v1.w};
    __align__(16) __nv_bfloat16 hv[8];
    __align__(16) __nv_bfloat16 lv[8];
    #pragma unroll
    for (int k = 0; k < 8; k++) {
        hv[k] = __float2bfloat16(vv[k]);
        lv[k] = __float2bfloat16(vv[k] - __bfloat162float(hv[k]));
    }
    *(uint4*)&g_wh[i] = *(uint4*)hv;
    *(uint4*)&g_wl[i] = *(uint4*)lv;
}

// ---------------------------------------------------------------------------
// bf16-split GEMM (mma.sync): Y[m,n] = sum_k A[m,k]*W[n,k] (+bias)
// CTA 128x128, BK=64, 256 thr, cp.async double buffer (128KB dyn smem).
// mode 0: -> g_qh/g_ql (scaled by QSCALE)   mode 1: -> g_kh/g_kl
// mode 2: A=Wv, W=x_b -> V^T split [B,H,D,T] (bias by m)
// mode 3: fp32 out [M,1024]
// ---------------------------------------------------------------------------
__global__ __launch_bounds__(256) void gemm_bf16(
    const __nv_bfloat16* __restrict__ Ah, const __nv_bfloat16* __restrict__ Al,
    const __nv_bfloat16* __restrict__ Wh, const __nv_bfloat16* __restrict__ Wl,
    const float* __restrict__ bias, float* __restrict__ out32,
    int mode, int bpar)
{
    extern __shared__ char dynsmem[];
    const uint32_t smem_u32 = (uint32_t)__cvta_generic_to_shared(dynsmem);

    const int tid  = threadIdx.x;
    const int lane = tid & 31;
    const int wid  = tid >> 5;
    const int warp_m = (wid >> 2) * 64;
    const int warp_n = (wid & 3) * 32;
    const int m0 = blockIdx.y * 128;
    const int n0 = blockIdx.x * 128;

    float acc[4][4][4];
    #pragma unroll
    for (int a = 0; a < 4; a++)
        #pragma unroll
        for (int b = 0; b < 4; b++)
            #pragma unroll
            for (int c = 0; c < 4; c++) acc[a][b][c] = 0.f;

    auto issue = [&](int stage, int kt) {
        const uint32_t sb = smem_u32 + stage * 65536;
        const int k0 = kt * 64;
        #pragma unroll
        for (int t = 0; t < 4; t++) {
            int id  = tid + t * 256;
            int row = id >> 3;
            int c   = id & 7;
            uint32_t soff = row * 128 + ((c ^ (row & 7)) << 4);
            long ga = (long)(m0 + row) * 1024 + k0 + c * 8;
            long gw = (long)(n0 + row) * 1024 + k0 + c * 8;
            cp16(sb +     0 + soff, Ah + ga);
            cp16(sb + 16384 + soff, Al + ga);
            cp16(sb + 32768 + soff, Wh + gw);
            cp16(sb + 49152 + soff, Wl + gw);
        }
    };

    issue(0, 0); CP_COMMIT();

    for (int kt = 0; kt < 16; kt++) {
        if (kt < 15) { issue((kt + 1) & 1, kt + 1); CP_COMMIT(); CP_WAIT1(); }
        else         { CP_WAIT0(); }
        __syncthreads();

        const uint32_t sb = smem_u32 + (kt & 1) * 65536;
        #pragma unroll
        for (int ks = 0; ks < 4; ks++) {
            uint32_t ah[4][4], al[4][4];
            #pragma unroll
            for (int mi = 0; mi < 4; mi++) {
                int m = warp_m + mi * 16 + ((lane >> 3) & 1) * 8 + (lane & 7);
                int c = ks * 2 + (lane >> 4);
                uint32_t off = m * 128 + ((c ^ (m & 7)) << 4);
                ldsm4(ah[mi], sb + off);
                ldsm4(al[mi], sb + 16384 + off);
            }
            uint32_t bh[4][2], bl[4][2];
            #pragma unroll
            for (int ni = 0; ni < 2; ni++) {
                int n = warp_n + ni * 16 + (lane >> 4) * 8 + (lane & 7);
                int c = ks * 2 + ((lane >> 3) & 1);
                uint32_t off = n * 128 + ((c ^ (n & 7)) << 4);
                uint32_t tmp[4];
                ldsm4(tmp, sb + 32768 + off);
                bh[2*ni][0] = tmp[0]; bh[2*ni][1] = tmp[1];
                bh[2*ni+1][0] = tmp[2]; bh[2*ni+1][1] = tmp[3];
                ldsm4(tmp, sb + 49152 + off);
                bl[2*ni][0] = tmp[0]; bl[2*ni][1] = tmp[1];
                bl[2*ni+1][0] = tmp[2]; bl[2*ni+1][1] = tmp[3];
            }
            // term-major: same-accumulator distance = 4 MMAs
            #pragma unroll
            for (int mi = 0; mi < 4; mi++) {
                #pragma unroll
                for (int j = 0; j < 4; j++) mma16816(acc[mi][j], ah[mi], bh[j]);
                #pragma unroll
                for (int j = 0; j < 4; j++) mma16816(acc[mi][j], ah[mi], bl[j]);
                #pragma unroll
                for (int j = 0; j < 4; j++) mma16816(acc[mi][j], al[mi], bh[j]);
            }
        }
        __syncthreads();
    }

    // --- epilogue ---
    #pragma unroll
    for (int mi = 0; mi < 4; mi++) {
        int m = m0 + warp_m + mi * 16 + (lane >> 2);
        #pragma unroll
        for (int j = 0; j < 4; j++) {
            int n = n0 + warp_n + j * 8 + (lane & 3) * 2;
            float v0, v1, v2, v3;
            if (mode == 2) {
                float bm0 = bias[m], bm1 = bias[m + 8];
                v0 = acc[mi][j][0] + bm0; v1 = acc[mi][j][1] + bm0;
                v2 = acc[mi][j][2] + bm1; v3 = acc[mi][j][3] + bm1;
            } else {
                float2 bv = *(const float2*)&bias[n];
                v0 = acc[mi][j][0] + bv.x; v1 = acc[mi][j][1] + bv.y;
                v2 = acc[mi][j][2] + bv.x; v3 = acc[mi][j][3] + bv.y;
            }
            if (mode == 0 || mode == 1) {
                if (mode == 0) { v0 *= QSCALE; v1 *= QSCALE; v2 *= QSCALE; v3 *= QSCALE; }
                __nv_bfloat16 *hi = (mode == 0) ? g_qh : g_kh;
                __nv_bfloat16 *lo = (mode == 0) ? g_ql : g_kl;
                int b = m >> 11, t = m & 2047;
                int h = n >> 6,  d = n & 63;
                size_t i0 = ((size_t)((b*HH + h)*TT + t))*DD + d;
                split2(v0, v1, hi, lo, i0);
                int t2 = (m + 8) & 2047;
                size_t i1 = ((size_t)((b*HH + h)*TT + t2))*DD + d;
                split2(v2, v3, hi, lo, i1);
            } else if (mode == 2) {
                int h = m >> 6, d = m & 63;
                size_t i0 = ((size_t)((bpar*HH + h)*DD + d))*TT + n;
                split2(v0, v1, g_vth, g_vtl, i0);
                int h2 = (m + 8) >> 6, d2 = (m + 8) & 63;
                size_t i1 = ((size_t)((bpar*HH + h2)*DD + d2))*TT + n;
                split2(v2, v3, g_vth, g_vtl, i1);
            } else {
                *(float2*)&out32[(long)m * 1024 + n]       = make_float2(v0, v1);
                *(float2*)&out32[(long)(m + 8) * 1024 + n] = make_float2(v2, v3);
            }
        }
    }
}

// ---------------------------------------------------------------------------
// Tensor-core flash attention (mma.sync bf16 split, fp32 softmax), causal.
// Changes vs R6: fragment-load software pipelining, term interleave, exp2f.
// ---------------------------------------------------------------------------
__global__ __launch_bounds__(256, 2) void attn_mma()
{
    extern __shared__ char dynsmem[];
    const uint32_t sb = (uint32_t)__cvta_generic_to_shared(dynsmem);
    const uint32_t QH = 0, QL = 16384, ST = 32768, STSZ = 32768;

    const int tid  = threadIdx.x;
    const int lane = tid & 31;
    const int wid  = tid >> 5;
    const int qi = (int)gridDim.x - 1 - (int)blockIdx.x;
    const int bh = blockIdx.y;
    const int ntiles = 2*qi + 2;
    const int wrow = wid * 16;

    const size_t qkbase = (size_t)bh * TT * DD;
    const size_t vbase  = (size_t)bh * DD * TT;

    {
        int row = (tid >> 3);
        int c   = tid & 7;
        #pragma unroll
        for (int t = 0; t < 4; t++) {
            int r = row + t * 32;
            uint32_t soff = r * 128 + ((c ^ (r & 7)) << 4);
            size_t g = (qkbase + (size_t)(qi*128 + r)*DD) + c*8;
            cp16(sb + QH + soff, g_qh + g);
            cp16(sb + QL + soff, g_ql + g);
        }
    }

    auto issue_tile = [&](int j) {
        const uint32_t base = sb + ST + (j & 1) * STSZ;
        const int kv0 = j * 64;
        int row = (tid >> 3);
        int c   = tid & 7;
        #pragma unroll
        for (int half = 0; half < 2; half++) {
            int r = row + half * 32;
            uint32_t soff = r * 128 + ((c ^ (r & 7)) << 4);
            size_t gk = (qkbase + (size_t)(kv0 + r)*DD) + c*8;
            size_t gv = (vbase  + (size_t)r*TT) + kv0 + c*8;
            cp16(base +     0 + soff, g_kh  + gk);
            cp16(base +  8192 + soff, g_kl  + gk);
            cp16(base + 16384 + soff, g_vth + gv);
            cp16(base + 24576 + soff, g_vtl + gv);
        }
    };

    issue_tile(0); CP_COMMIT();

    float o[8][4];
    #pragma unroll
    for (int j = 0; j < 8; j++)
        #pragma unroll
        for (int e = 0; e < 4; e++) o[j][e] = 0.f;
    float m0 = -1e30f, m1 = -1e30f, l0 = 0.f, l1 = 0.f;

    const int r0g = qi*128 + wrow + (lane >> 2);
    const int r1g = r0g + 8;
    const int nk = (lane >> 4) * 8 + (lane & 7);

    for (int j = 0; j < ntiles; j++) {
        if (j + 1 < ntiles) { issue_tile(j + 1); CP_COMMIT(); CP_WAIT1(); }
        else                { CP_WAIT0(); }
        __syncthreads();

        const uint32_t base = sb + ST + (j & 1) * STSZ;

        // ---- S = Q K^T (pipelined ldsm, interleaved terms) ----
        float s[8][4];
        #pragma unroll
        for (int t = 0; t < 8; t++)
            #pragma unroll
            for (int e = 0; e < 4; e++) s[t][e] = 0.f;

        #pragma unroll
        for (int ks = 0; ks < 4; ks++) {
            uint32_t qh[4], ql[4];
            int mq = wrow + ((lane >> 3) & 1) * 8 + (lane & 7);
            int cq = ks * 2 + (lane >> 4);
            uint32_t qoff = mq * 128 + ((cq ^ (mq & 7)) << 4);
            ldsm4(qh, sb + QH + qoff);
            ldsm4(ql, sb + QL + qoff);
            const int ck = ks * 2 + ((lane >> 3) & 1);
            uint32_t koff[4];
            #pragma unroll
            for (int np = 0; np < 4; np++) {
                int n = np * 16 + nk;
                koff[np] = n * 128 + ((ck ^ (n & 7)) << 4);
            }
            uint32_t khc[4], khn[4], klc[4];
            ldsm4(khc, base + koff[0]);
            #pragma unroll
            for (int np = 0; np < 4; np++) {
                ldsm4(klc, base + 8192 + koff[np]);       // used 4 MMAs later
                if (np < 3) ldsm4(khn, base + koff[np+1]); // next-iter prefetch
                float* A = s[2*np]; float* B = s[2*np+1];
                mma16816(A, qh, khc);   mma16816(B, qh, khc+2);
                mma16816(A, ql, khc);   mma16816(B, ql, khc+2);
                mma16816(A, qh, klc);   mma16816(B, qh, klc+2);
                #pragma unroll
                for (int e = 0; e < 4; e++) khc[e] = khn[e];
            }
        }

        // ---- causal mask ----
        const int kv0 = j * 64;
        if (kv0 + 63 > r0g) {
            #pragma unroll
            for (int t = 0; t < 8; t++) {
                int colb = kv0 + t*8 + (lane & 3)*2;
                #pragma unroll
                for (int e = 0; e < 2; e++) {
                    if (colb + e > r0g) s[t][e]   = -1e30f;
                    if (colb + e > r1g) s[t][2+e] = -1e30f;
                }
            }
        }

        // ---- online softmax (log2 domain, exp2f = single MUFU.EX2) ----
        float mx0 = -1e30f, mx1 = -1e30f;
        #pragma unroll
        for (int t = 0; t < 8; t++) {
            mx0 = fmaxf(mx0, fmaxf(s[t][0], s[t][1]));
            mx1 = fmaxf(mx1, fmaxf(s[t][2], s[t][3]));
        }
        mx0 = fmaxf(mx0, __shfl_xor_sync(0xffffffffu, mx0, 1));
        mx0 = fmaxf(mx0, __shfl_xor_sync(0xffffffffu, mx0, 2));
        mx1 = fmaxf(mx1, __shfl_xor_sync(0xffffffffu, mx1, 1));
        mx1 = fmaxf(mx1, __shfl_xor_sync(0xffffffffu, mx1, 2));
        float mn0 = fmaxf(m0, mx0), mn1 = fmaxf(m1, mx1);
        float a0 = exp2f(m0 - mn0), a1 = exp2f(m1 - mn1);
        float rs0 = 0.f, rs1 = 0.f;
        #pragma unroll
        for (int t = 0; t < 8; t++) {
            s[t][0] = exp2f(s[t][0] - mn0); rs0 += s[t][0];
            s[t][1] = exp2f(s[t][1] - mn0); rs0 += s[t][1];
            s[t][2] = exp2f(s[t][2] - mn1); rs1 += s[t][2];
            s[t][3] = exp2f(s[t][3] - mn1); rs1 += s[t][3];
        }
        rs0 += __shfl_xor_sync(0xffffffffu, rs0, 1);
        rs0 += __shfl_xor_sync(0xffffffffu, rs0, 2);
        rs1 += __shfl_xor_sync(0xffffffffu, rs1, 1);
        rs1 += __shfl_xor_sync(0xffffffffu, rs1, 2);
        l0 = l0 * a0 + rs0; l1 = l1 * a1 + rs1;
        m0 = mn0; m1 = mn1;
        #pragma unroll
        for (int t = 0; t < 8; t++) {
            o[t][0] *= a0; o[t][1] *= a0;
            o[t][2] *= a1; o[t][3] *= a1;
        }

        // ---- O += P V (pipelined ldsm, interleaved terms) ----
        #pragma unroll
        for (int ks = 0; ks < 4; ks++) {
            const int ck = ks * 2 + ((lane >> 3) & 1);
            uint32_t voff[4];
            #pragma unroll
            for (int np = 0; np < 4; np++) {
                int n = np * 16 + nk;
                voff[np] = n * 128 + ((ck ^ (n & 7)) << 4);
            }
            uint32_t vhc[4], vhn[4], vlc[4];
            ldsm4(vhc, base + 16384 + voff[0]);   // hides under P packing below

            uint32_t ph[4], pl[4];
            #pragma unroll
            for (int h2 = 0; h2 < 2; h2++) {
                int t = 2*ks + h2;
                float v0 = s[t][0], v1 = s[t][1], v2 = s[t][2], v3 = s[t][3];
                uint32_t p01 = pack2(v0, v1);
                uint32_t p23 = pack2(v2, v3);
                ph[2*h2]   = p01;
                ph[2*h2+1] = p23;
                __nv_bfloat162 b01 = *(__nv_bfloat162*)&p01;
                __nv_bfloat162 b23 = *(__nv_bfloat162*)&p23;
                pl[2*h2]   = pack2(v0 - __bfloat162float(b01.x), v1 - __bfloat162float(b01.y));
                pl[2*h2+1] = pack2(v2 - __bfloat162float(b23.x), v3 - __bfloat162float(b23.y));
            }

            #pragma unroll
            for (int np = 0; np < 4; np++) {
                ldsm4(vlc, base + 24576 + voff[np]);         // used 4 MMAs later
                if (np < 3) ldsm4(vhn, base + 16384 + voff[np+1]);
                float* A = o[2*np]; float* B = o[2*np+1];
                mma16816(A, ph, vhc);   mma16816(B, ph, vhc+2);
                mma16816(A, pl, vhc);   mma16816(B, pl, vhc+2);
                mma16816(A, ph, vlc);   mma16816(B, ph, vlc+2);
                #pragma unroll
                for (int e = 0; e < 4; e++) vhc[e] = vhn[e];
            }
        }
        __syncthreads();
    }

    // ---- epilogue ----
    float inv0 = 1.0f / l0, inv1 = 1.0f / l1;
    const int b = bh >> 4, h = bh & 15;
    #pragma unroll
    for (int t = 0; t < 8; t++) {
        int d = t*8 + (lane & 3)*2;
        size_t i0 = ((size_t)(b*TT + r0g)*HH + h)*DD + d;
        size_t i1 = ((size_t)(b*TT + r1g)*HH + h)*DD + d;
        split2(o[t][0]*inv0, o[t][1]*inv0, g_ath, g_atl, i0);
        split2(o[t][2]*inv1, o[t][3]*inv1, g_ath, g_atl, i1);
    }
}

// ---------------------------------------------------------------------------
extern "C" void kernel_launch(void* const* d_in, const int* in_sizes, int n_in,
                              void* d_out, int out_size)
{
    (void)in_sizes; (void)n_in; (void)out_size;
    const float* x  = (const float*)d_in[0];
    const float* Wq = (const float*)d_in[1];
    const float* bq = (const float*)d_in[2];
    const float* Wk = (const float*)d_in[3];
    const float* bk = (const float*)d_in[4];
    const float* Wv = (const float*)d_in[5];
    const float* bv = (const float*)d_in[6];
    const float* Wp = (const float*)d_in[7];
    const float* bp = (const float*)d_in[8];
    float* out = (float*)d_out;

    static bool attr_done = false;
    if (!attr_done) {
        cudaFuncSetAttribute(gemm_bf16,
            cudaFuncAttributeMaxDynamicSharedMemorySize, 131072);
        cudaFuncSetAttribute(attn_mma,
            cudaFuncAttributeMaxDynamicSharedMemorySize, 98304);
        attr_done = true;
    }

    static __nv_bfloat16 *xh=nullptr,*xl=nullptr,*wh=nullptr,*wl=nullptr,*ath=nullptr,*atl=nullptr;
    if (!xh) {
        cudaGetSymbolAddress((void**)&xh,  g_xh);
        cudaGetSymbolAddress((void**)&xl,  g_xl);
        cudaGetSymbolAddress((void**)&wh,  g_wh);
        cudaGetSymbolAddress((void**)&wl,  g_wl);
        cudaGetSymbolAddress((void**)&ath, g_ath);
        cudaGetSymbolAddress((void**)&atl, g_atl);
    }

    split_x<<<(MROWS*CC)/8/256, 256>>>(x);
    split_w4<<<(4*CC*CC)/8/256, 256>>>(Wq, Wk, Wv, Wp);

    dim3 pgrid(CC/128, MROWS/128);   // (8, 32)
    dim3 vgrid(TT/128, CC/128);      // (16, 8)
    gemm_bf16<<<pgrid, 256, 131072>>>(xh, xl, wh + 0*CC*CC, wl + 0*CC*CC, bq, nullptr, 0, 0);
    gemm_bf16<<<pgrid, 256, 131072>>>(xh, xl, wh + 1*CC*CC, wl + 1*CC*CC, bk, nullptr, 1, 0);
    gemm_bf16<<<vgrid, 256, 131072>>>(wh + 2*CC*CC, wl + 2*CC*CC, xh,         xl,         bv, nullptr, 2, 0);
    gemm_bf16<<<vgrid, 256, 131072>>>(wh + 2*CC*CC, wl + 2*CC*CC, xh + TT*CC, xl + TT*CC, bv, nullptr, 2, 1);

    attn_mma<<<dim3(TT/128, BB*HH), 256, 98304>>>();

    gemm_bf16<<<pgrid, 256, 131072>>>(ath, atl, wh + 3*CC*CC, wl + 3*CC*CC, bp, out, 3, 0);
}